// round 7
// baseline (speedup 1.0000x reference)
#include <cuda_runtime.h>
#include <cstdint>

#define NB     16
#define NTAU   10
#define ND     6
#define NN     512
#define NW     9
#define NHID   64
#define KC     54
#define TILE_M 128
#define TPB    256
#define NTILE  64
#define CHUNK  32
#define DYN_BYTES (98304 + 128)

typedef unsigned long long ull;

// W0 pre-converted: [i*10+t] tiles of 16KB (8KB hi + 8KB lo plane), swizzled [n][kk] bf16
__device__ __align__(1024) unsigned char g_w0bf[60 * 16384];
// A scratch: per (tile, i*10+t): 32KB (16KB hi plane + 16KB lo plane), swizzled [row][kk] bf16
__device__ __align__(1024) unsigned char g_a[(size_t)NTILE * 60 * 32768];

__device__ __forceinline__ uint32_t smem_u32(const void* p) {
    uint32_t a;
    asm("{ .reg .u64 t; cvta.to.shared.u64 t, %1; cvt.u32.u64 %0, t; }" : "=r"(a) : "l"(p));
    return a;
}
__device__ __forceinline__ ull ffma2(ull a, ull b, ull c) {
    ull d; asm("fma.rn.f32x2 %0, %1, %2, %3;" : "=l"(d) : "l"(a), "l"(b), "l"(c)); return d;
}
__device__ __forceinline__ ull pack2(float x) {
    ull d; asm("mov.b64 %0, {%1, %1};" : "=l"(d) : "f"(x)); return d;
}
__device__ __forceinline__ float2 unpack2(ull v) {
    float2 r; asm("mov.b64 {%0, %1}, %2;" : "=f"(r.x), "=f"(r.y) : "l"(v)); return r;
}
__device__ __forceinline__ uint32_t f2bf_bits(float v) {   // RNE bf16
    uint32_t u = __float_as_uint(v);
    return (u + 0x7FFFu + ((u >> 16) & 1u)) >> 16;
}
__device__ __forceinline__ uint32_t cvt_bf16x2(float hi, float lo) {
    uint32_t r; asm("cvt.rn.bf16x2.f32 %0, %1, %2;" : "=r"(r) : "f"(hi), "f"(lo)); return r;
}
__device__ __forceinline__ float2 ldcs2(const float2* p) {
    float2 r; asm volatile("ld.global.cs.v2.f32 {%0,%1}, [%2];" : "=f"(r.x), "=f"(r.y) : "l"(p)); return r;
}
__device__ __forceinline__ void ldsm4(uint32_t a, uint32_t& r0, uint32_t& r1, uint32_t& r2, uint32_t& r3) {
    asm volatile("ldmatrix.sync.aligned.m8n8.x4.shared.b16 {%0,%1,%2,%3}, [%4];"
                 : "=r"(r0), "=r"(r1), "=r"(r2), "=r"(r3) : "r"(a));
}
__device__ __forceinline__ void mma_bf16(float* d, uint32_t a0, uint32_t a1, uint32_t a2, uint32_t a3,
                                         uint32_t b0, uint32_t b1) {
    asm volatile("mma.sync.aligned.m16n8k16.row.col.f32.bf16.bf16.f32 "
                 "{%0,%1,%2,%3}, {%4,%5,%6,%7}, {%8,%9}, {%0,%1,%2,%3};"
                 : "+f"(d[0]), "+f"(d[1]), "+f"(d[2]), "+f"(d[3])
                 : "r"(a0), "r"(a1), "r"(a2), "r"(a3), "r"(b0), "r"(b1));
}
#define CP16(dst, src) asm volatile("cp.async.cg.shared.global [%0], [%1], 16;" :: "r"(dst), "l"(src))
#define CP_COMMIT()    asm volatile("cp.async.commit_group;" ::: "memory")
#define CP_WAIT0()     asm volatile("cp.async.wait_group 0;" ::: "memory")
#define CP_WAIT1()     asm volatile("cp.async.wait_group 1;" ::: "memory")

// ------------ producer: m -> swizzled bf16 hi/lo A-tile images (+ W0 prep on first chunk) ------------
__global__ __launch_bounds__(TPB) void produce_a(
    const float* __restrict__ x,
    const float* __restrict__ mask_param,
    const float* __restrict__ u,
    const float* __restrict__ W0,
    int tile_base, int do_w0)
{
    __shared__ float E_s[KC];
    __shared__ float x_s[1632];
    __shared__ unsigned char lut_s[KC];

    const int tid  = threadIdx.x;
    const int tile = blockIdx.x + tile_base;
    const int itx  = blockIdx.y;          // i*10 + t
    const int i = itx / 10, t = itx % 10;
    const int tile0 = tile * TILE_M;
    const int n0 = tile0 >> 4;

    // fold W0 prep: chunk-0, tile-local-0 blocks each convert one W0 tile
    if (do_w0 && blockIdx.x == 0) {
        const float* src = W0 + ((size_t)i * 540 + t * KC) * NHID;
        unsigned char* hi = g_w0bf + (size_t)itx * 16384;
        unsigned char* lo = hi + 8192;
        for (int e = tid; e < 4096; e += TPB) {
            int kk = e >> 6, n = e & 63;
            float v = (kk < KC) ? src[kk * 64 + n] : 0.f;
            uint32_t hb = f2bf_bits(v);
            float hf = __uint_as_float(hb << 16);
            uint32_t lb = f2bf_bits(v - hf);
            uint32_t off = (uint32_t)(n * 128 + kk * 2) ^ ((uint32_t)(n & 7) << 4);
            *(uint16_t*)(hi + off) = (uint16_t)hb;
            *(uint16_t*)(lo + off) = (uint16_t)lb;
        }
    }

    if (tid < KC) {
        E_s[tid] = __expf(-mask_param[(t * ND + i) * KC + tid]);
        lut_s[tid] = (unsigned char)((tid / NW) * 16 + tid % NW);
    }
    #pragma unroll
    for (int e6 = 0; e6 < 6; ++e6) {
        int e = tid + e6 * 256;
        int colw = e & 15;
        int j = (e >> 4) % 6;
        int bb = e / 96;
        int col = n0 + colw - 4;
        float v = 0.f;
        if ((unsigned)col < NN) v = x[((bb * NTAU + t) * ND + j) * NN + col];
        x_s[(j * 16 + colw) * 17 + bb] = v;
    }
    float2 ur[14];
    #pragma unroll
    for (int it = 0; it < 14; ++it) {
        int p = tid + it * 256;
        if (p < 3456) {
            int r = (p * 4855) >> 17;         // p/27
            int q = p - r * 27;
            ur[it] = ldcs2((const float2*)(u + (size_t)(tile0 + r) * 3240 + (t * ND + i) * KC + 2 * q));
        }
    }
    __syncthreads();

    unsigned char* ahp = g_a + ((size_t)tile * 60 + itx) * 32768;
    #pragma unroll
    for (int it = 0; it < 14; ++it) {
        int p = tid + it * 256;
        if (p < 3456) {
            int r = (p * 4855) >> 17;
            int q = p - r * 27;
            int kk = 2 * q;
            float2 uv = ur[it];
            float2 ev = *(const float2*)&E_s[kk];
            int nl = r >> 4, bb = r & 15;
            float x0 = x_s[(lut_s[kk] + nl) * 17 + bb];
            float x1 = x_s[(lut_s[kk + 1] + nl) * 17 + bb];
            float m0 = x0 * __fdividef(uv.x, fmaf(ev.x, 1.f - uv.x, uv.x));
            float m1 = x1 * __fdividef(uv.y, fmaf(ev.y, 1.f - uv.y, uv.y));
            uint32_t h2 = cvt_bf16x2(m1, m0);           // lo16 = m0
            float hf0 = __uint_as_float(h2 << 16);
            float hf1 = __uint_as_float(h2 & 0xFFFF0000u);
            uint32_t l2 = cvt_bf16x2(m1 - hf1, m0 - hf0);
            uint32_t off = (uint32_t)(r * 128 + 4 * q) ^ ((uint32_t)(r & 7) << 4);
            *(uint32_t*)(ahp + off)         = h2;   // default policy: keep in L2 for consumer
            *(uint32_t*)(ahp + 16384 + off) = l2;
        }
    }
}

// ------------ consumer: GEMM (tensor cores) + layers 1/2 ------------
__global__ __launch_bounds__(TPB, 2)
void gemm_mlp(const float* __restrict__ b0,
              const float* __restrict__ W1,
              const float* __restrict__ b1,
              const float* __restrict__ W2,
              const float* __restrict__ b2,
              float* __restrict__ out,
              int tile_base)
{
    extern __shared__ unsigned char dyn_raw[];
    __shared__ float b0_s[NHID], b1_s[NHID], W2_s[128], b2_s[2];
    __shared__ float2 po_s[TPB];

    const uint32_t raw_u = smem_u32(dyn_raw);
    const uint32_t dynb  = (raw_u + 127u) & ~127u;
    unsigned char* dyn = dyn_raw + (dynb - raw_u);

    const int tid  = threadIdx.x;
    const int w    = tid >> 5;
    const int lane = tid & 31;
    const int i    = blockIdx.y;
    const int tile = blockIdx.x + tile_base;
    const int tile0 = tile * TILE_M;

    if (tid < NHID) { b0_s[tid] = b0[i * NHID + tid]; b1_s[tid] = b1[i * NHID + tid]; }
    if (tid < 128) W2_s[tid] = W2[i * 128 + tid];
    if (tid < 2)   b2_s[tid] = b2[i * 2 + tid];

    float d[8][4];
    #pragma unroll
    for (int q = 0; q < 8; ++q)
        #pragma unroll
        for (int c = 0; c < 4; ++c) d[q][c] = 0.f;

    // per-lane ldmatrix geometry
    const int rowA = (w << 4) + (lane & 15);
    const uint32_t aoff = (uint32_t)rowA * 128;
    const uint32_t axr  = (uint32_t)(rowA & 7) << 4;
    const int nB_ = lane & 15;
    const uint32_t bxr  = (uint32_t)(nB_ & 7) << 4;
    const uint32_t colsel = (uint32_t)(lane >> 4) << 4;

    auto prefetch = [&](int t) {
        const unsigned char* asrc = g_a + ((size_t)tile * 60 + i * 10 + t) * 32768;
        uint32_t adst = dynb + (uint32_t)(t & 1) * 32768;
        #pragma unroll
        for (int c = 0; c < 8; ++c)
            CP16(adst + tid * 16 + c * 4096, asrc + tid * 16 + c * 4096);
        const unsigned char* bsrc = g_w0bf + (size_t)(i * 10 + t) * 16384;
        uint32_t bdst = dynb + 65536 + (uint32_t)(t & 1) * 16384;
        #pragma unroll
        for (int c = 0; c < 4; ++c)
            CP16(bdst + tid * 16 + c * 4096, bsrc + tid * 16 + c * 4096);
        CP_COMMIT();
    };
    auto consume = [&](int s) {
        uint32_t Abase = dynb + (uint32_t)s * 32768;
        uint32_t Bbase = dynb + 65536 + (uint32_t)s * 16384;
        #pragma unroll
        for (int k = 0; k < 4; ++k) {
            uint32_t colb = (uint32_t)k * 32 + colsel;
            uint32_t aa = Abase + aoff + (colb ^ axr);
            uint32_t ah0, ah1, ah2, ah3, al0, al1, al2, al3;
            ldsm4(aa,         ah0, ah1, ah2, ah3);
            ldsm4(aa + 16384, al0, al1, al2, al3);
            #pragma unroll
            for (int g = 0; g < 4; ++g) {
                uint32_t ba = Bbase + ((uint32_t)g << 11) + (uint32_t)nB_ * 128 + (colb ^ bxr);
                uint32_t bh0, bh1, bh2, bh3, bl0, bl1, bl2, bl3;
                ldsm4(ba,        bh0, bh1, bh2, bh3);
                ldsm4(ba + 8192, bl0, bl1, bl2, bl3);
                mma_bf16(d[2 * g],     ah0, ah1, ah2, ah3, bh0, bh2);
                mma_bf16(d[2 * g],     al0, al1, al2, al3, bh0, bh2);
                mma_bf16(d[2 * g],     ah0, ah1, ah2, ah3, bl0, bl2);
                mma_bf16(d[2 * g + 1], ah0, ah1, ah2, ah3, bh1, bh3);
                mma_bf16(d[2 * g + 1], al0, al1, al2, al3, bh1, bh3);
                mma_bf16(d[2 * g + 1], ah0, ah1, ah2, ah3, bl1, bl3);
            }
        }
    };

    prefetch(0);
    prefetch(1);
    for (int t = 0; t < NTAU; ++t) {
        if (t < NTAU - 1) CP_WAIT1(); else CP_WAIT0();
        __syncthreads();
        consume(t & 1);
        __syncthreads();
        if (t < NTAU - 2) prefetch(t + 2);
    }

    // ---------- epilogue: bias+relu -> h_s (stride 68), stage W1 ----------
    {
        float* hs = (float*)dyn;
        int rb = (w << 4) + (lane >> 2);
        int cb = (lane & 3) * 2;
        #pragma unroll
        for (int nt = 0; nt < 8; ++nt) {
            int c = nt * 8 + cb;
            float ba = b0_s[c], bbv = b0_s[c + 1];
            *(float2*)&hs[rb * 68 + c]       = make_float2(fmaxf(d[nt][0] + ba, 0.f), fmaxf(d[nt][1] + bbv, 0.f));
            *(float2*)&hs[(rb + 8) * 68 + c] = make_float2(fmaxf(d[nt][2] + ba, 0.f), fmaxf(d[nt][3] + bbv, 0.f));
        }
        const unsigned char* w1src = (const unsigned char*)(W1 + (size_t)i * NHID * NHID);
        uint32_t w1dst = dynb + 65536;
        #pragma unroll
        for (int c = 0; c < 4; ++c)
            CP16(w1dst + tid * 16 + c * 4096, w1src + tid * 16 + c * 4096);
        CP_COMMIT();
        CP_WAIT0();
    }
    __syncthreads();

    // ---------- layers 1+2: 2 threads per token, split output-half ----------
    {
        const float* hs  = (const float*)dyn;
        const float* W1s = (const float*)(dyn + 65536);
        int r = tid >> 1, half = tid & 1;
        float h[NHID];
        {
            float4* hv = (float4*)h;
            const float4* src = (const float4*)(hs + r * 68);
            #pragma unroll
            for (int q = 0; q < 16; ++q) hv[q] = src[q];
        }
        ull acc2[16];
        #pragma unroll
        for (int p = 0; p < 16; ++p) acc2[p] = 0ULL;
        #pragma unroll 8
        for (int k = 0; k < NHID; ++k) {
            ull hdup = pack2(h[k]);
            const ulonglong2* wr = (const ulonglong2*)(W1s + k * NHID + half * 32);
            #pragma unroll
            for (int q = 0; q < 8; ++q) {
                ulonglong2 wv = wr[q];
                acc2[2 * q]     = ffma2(hdup, wv.x, acc2[2 * q]);
                acc2[2 * q + 1] = ffma2(hdup, wv.y, acc2[2 * q + 1]);
            }
        }
        float o0 = half ? 0.f : b2_s[0];
        float o1 = half ? 0.f : b2_s[1];
        #pragma unroll
        for (int p = 0; p < 16; ++p) {
            float2 v = unpack2(acc2[p]);
            int g0 = half * 32 + 2 * p;
            float v0 = fmaxf(v.x + b1_s[g0], 0.f);
            float v1 = fmaxf(v.y + b1_s[g0 + 1], 0.f);
            o0 = fmaf(v0, W2_s[g0 * 2],     o0);
            o1 = fmaf(v0, W2_s[g0 * 2 + 1], o1);
            o0 = fmaf(v1, W2_s[g0 * 2 + 2], o0);
            o1 = fmaf(v1, W2_s[g0 * 2 + 3], o1);
        }
        po_s[tid] = make_float2(o0, o1);
    }
    __syncthreads();
    if (tid < TILE_M) {
        float2 pa = po_s[2 * tid], pb = po_s[2 * tid + 1];
        int token = tile0 + tid;
        int bb = token & (NB - 1);
        int nn = token >> 4;
        ((float2*)out)[(size_t)(bb * ND + i) * NN + nn] = make_float2(pa.x + pb.x, pa.y + pb.y);
    }
}

extern "C" void kernel_launch(void* const* d_in, const int* in_sizes, int n_in,
                              void* d_out, int out_size)
{
    const float* x  = (const float*)d_in[0];
    const float* mp = (const float*)d_in[1];
    const float* u  = (const float*)d_in[2];
    const float* W0 = (const float*)d_in[3];
    const float* b0 = (const float*)d_in[4];
    const float* W1 = (const float*)d_in[5];
    const float* b1 = (const float*)d_in[6];
    const float* W2 = (const float*)d_in[7];
    const float* b2 = (const float*)d_in[8];
    float* out = (float*)d_out;

    static int smem_set = 0;
    if (!smem_set) {
        cudaFuncSetAttribute(gemm_mlp, cudaFuncAttributeMaxDynamicSharedMemorySize, DYN_BYTES);
        smem_set = 1;
    }
    produce_a<<<dim3(CHUNK, 60), TPB>>>(x, mp, u, W0, 0, 1);
    gemm_mlp<<<dim3(CHUNK, ND), TPB, DYN_BYTES>>>(b0, W1, b1, W2, b2, out, 0);
    produce_a<<<dim3(CHUNK, 60), TPB>>>(x, mp, u, W0, CHUNK, 0);
    gemm_mlp<<<dim3(CHUNK, ND), TPB, DYN_BYTES>>>(b0, W1, b1, W2, b2, out, CHUNK);
}

// round 8
// speedup vs baseline: 1.0626x; 1.0626x over previous
#include <cuda_runtime.h>
#include <cstdint>

#define NB     16
#define NTAU   10
#define ND     6
#define NN     512
#define NW     9
#define NHID   64
#define KC     54
#define TILE_M 128
#define TPB    256
#define NTILE  64
#define CHUNK  16
#define NCHUNK 4
#define DYN_BYTES (98304 + 128)

typedef unsigned long long ull;

// W0 pre-converted: [i*10+t] tiles of 16KB (8KB hi + 8KB lo plane), swizzled [n][kk] bf16
__device__ __align__(1024) unsigned char g_w0bf[60 * 16384];
// A scratch: per (tile, i*10+t): 32KB (16KB hi plane + 16KB lo plane), swizzled [row][kk] bf16
__device__ __align__(1024) unsigned char g_a[(size_t)NTILE * 60 * 32768];

__device__ __forceinline__ uint32_t smem_u32(const void* p) {
    uint32_t a;
    asm("{ .reg .u64 t; cvta.to.shared.u64 t, %1; cvt.u32.u64 %0, t; }" : "=r"(a) : "l"(p));
    return a;
}
__device__ __forceinline__ ull ffma2(ull a, ull b, ull c) {
    ull d; asm("fma.rn.f32x2 %0, %1, %2, %3;" : "=l"(d) : "l"(a), "l"(b), "l"(c)); return d;
}
__device__ __forceinline__ ull pack2(float x) {
    ull d; asm("mov.b64 %0, {%1, %1};" : "=l"(d) : "f"(x)); return d;
}
__device__ __forceinline__ float2 unpack2(ull v) {
    float2 r; asm("mov.b64 {%0, %1}, %2;" : "=f"(r.x), "=f"(r.y) : "l"(v)); return r;
}
__device__ __forceinline__ uint32_t f2bf_bits(float v) {   // RNE bf16
    uint32_t u = __float_as_uint(v);
    return (u + 0x7FFFu + ((u >> 16) & 1u)) >> 16;
}
__device__ __forceinline__ uint32_t cvt_bf16x2(float hi, float lo) {
    uint32_t r; asm("cvt.rn.bf16x2.f32 %0, %1, %2;" : "=r"(r) : "f"(hi), "f"(lo)); return r;
}
__device__ __forceinline__ float2 ldcs2(const float2* p) {
    float2 r; asm volatile("ld.global.cs.v2.f32 {%0,%1}, [%2];" : "=f"(r.x), "=f"(r.y) : "l"(p)); return r;
}
__device__ __forceinline__ void ldsm4(uint32_t a, uint32_t& r0, uint32_t& r1, uint32_t& r2, uint32_t& r3) {
    asm volatile("ldmatrix.sync.aligned.m8n8.x4.shared.b16 {%0,%1,%2,%3}, [%4];"
                 : "=r"(r0), "=r"(r1), "=r"(r2), "=r"(r3) : "r"(a));
}
__device__ __forceinline__ void mma_bf16(float* d, uint32_t a0, uint32_t a1, uint32_t a2, uint32_t a3,
                                         uint32_t b0, uint32_t b1) {
    asm volatile("mma.sync.aligned.m16n8k16.row.col.f32.bf16.bf16.f32 "
                 "{%0,%1,%2,%3}, {%4,%5,%6,%7}, {%8,%9}, {%0,%1,%2,%3};"
                 : "+f"(d[0]), "+f"(d[1]), "+f"(d[2]), "+f"(d[3])
                 : "r"(a0), "r"(a1), "r"(a2), "r"(a3), "r"(b0), "r"(b1));
}
#define CP16(dst, src) asm volatile("cp.async.cg.shared.global [%0], [%1], 16;" :: "r"(dst), "l"(src))
#define CP_COMMIT()    asm volatile("cp.async.commit_group;" ::: "memory")
#define CP_WAIT0()     asm volatile("cp.async.wait_group 0;" ::: "memory")
#define CP_WAIT1()     asm volatile("cp.async.wait_group 1;" ::: "memory")

// ------------ producer: m -> swizzled bf16 hi/lo A-tile images (+ W0 prep on first chunk) ------------
__global__ __launch_bounds__(TPB) void produce_a(
    const float* __restrict__ x,
    const float* __restrict__ mask_param,
    const float* __restrict__ u,
    const float* __restrict__ W0,
    int tile_base, int do_w0)
{
    __shared__ float E_s[KC];
    __shared__ float x_s[1632];
    __shared__ unsigned char lut_s[KC];

    const int tid  = threadIdx.x;
    const int tile = blockIdx.x + tile_base;
    const int itx  = blockIdx.y;          // i*10 + t
    const int i = itx / 10, t = itx % 10;
    const int tile0 = tile * TILE_M;
    const int n0 = tile0 >> 4;

    // fold W0 prep: chunk-0, tile-local-0 blocks each convert one W0 tile
    if (do_w0 && blockIdx.x == 0) {
        const float* src = W0 + ((size_t)i * 540 + t * KC) * NHID;
        unsigned char* hi = g_w0bf + (size_t)itx * 16384;
        unsigned char* lo = hi + 8192;
        for (int e = tid; e < 4096; e += TPB) {
            int kk = e >> 6, n = e & 63;
            float v = (kk < KC) ? src[kk * 64 + n] : 0.f;
            uint32_t hb = f2bf_bits(v);
            float hf = __uint_as_float(hb << 16);
            uint32_t lb = f2bf_bits(v - hf);
            uint32_t off = (uint32_t)(n * 128 + kk * 2) ^ ((uint32_t)(n & 7) << 4);
            *(uint16_t*)(hi + off) = (uint16_t)hb;
            *(uint16_t*)(lo + off) = (uint16_t)lb;
        }
    }

    if (tid < KC) {
        E_s[tid] = __expf(-mask_param[(t * ND + i) * KC + tid]);
        lut_s[tid] = (unsigned char)((tid / NW) * 16 + tid % NW);
    }
    #pragma unroll
    for (int e6 = 0; e6 < 6; ++e6) {
        int e = tid + e6 * 256;
        int colw = e & 15;
        int j = (e >> 4) % 6;
        int bb = e / 96;
        int col = n0 + colw - 4;
        float v = 0.f;
        if ((unsigned)col < NN) v = x[((bb * NTAU + t) * ND + j) * NN + col];
        x_s[(j * 16 + colw) * 17 + bb] = v;
    }
    float2 ur[14];
    #pragma unroll
    for (int it = 0; it < 14; ++it) {
        int p = tid + it * 256;
        if (p < 3456) {
            int r = (p * 4855) >> 17;         // p/27
            int q = p - r * 27;
            ur[it] = ldcs2((const float2*)(u + (size_t)(tile0 + r) * 3240 + (t * ND + i) * KC + 2 * q));
        }
    }
    __syncthreads();

    unsigned char* ahp = g_a + ((size_t)tile * 60 + itx) * 32768;
    #pragma unroll
    for (int it = 0; it < 14; ++it) {
        int p = tid + it * 256;
        if (p < 3456) {
            int r = (p * 4855) >> 17;
            int q = p - r * 27;
            int kk = 2 * q;
            float2 uv = ur[it];
            float2 ev = *(const float2*)&E_s[kk];
            int nl = r >> 4, bb = r & 15;
            float x0 = x_s[(lut_s[kk] + nl) * 17 + bb];
            float x1 = x_s[(lut_s[kk + 1] + nl) * 17 + bb];
            float m0 = x0 * __fdividef(uv.x, fmaf(ev.x, 1.f - uv.x, uv.x));
            float m1 = x1 * __fdividef(uv.y, fmaf(ev.y, 1.f - uv.y, uv.y));
            uint32_t h2 = cvt_bf16x2(m1, m0);           // lo16 = m0
            float hf0 = __uint_as_float(h2 << 16);
            float hf1 = __uint_as_float(h2 & 0xFFFF0000u);
            uint32_t l2 = cvt_bf16x2(m1 - hf1, m0 - hf0);
            uint32_t off = (uint32_t)(r * 128 + 4 * q) ^ ((uint32_t)(r & 7) << 4);
            *(uint32_t*)(ahp + off)         = h2;   // default policy: keep in L2 for consumer
            *(uint32_t*)(ahp + 16384 + off) = l2;
        }
    }
}

// ------------ consumer: GEMM (tensor cores) + layers 1/2 ------------
__global__ __launch_bounds__(TPB, 2)
void gemm_mlp(const float* __restrict__ b0,
              const float* __restrict__ W1,
              const float* __restrict__ b1,
              const float* __restrict__ W2,
              const float* __restrict__ b2,
              float* __restrict__ out,
              int tile_base)
{
    extern __shared__ unsigned char dyn_raw[];
    __shared__ float b0_s[NHID], b1_s[NHID], W2_s[128], b2_s[2];
    __shared__ float2 po_s[TPB];

    const uint32_t raw_u = smem_u32(dyn_raw);
    const uint32_t dynb  = (raw_u + 127u) & ~127u;
    unsigned char* dyn = dyn_raw + (dynb - raw_u);

    const int tid  = threadIdx.x;
    const int w    = tid >> 5;
    const int lane = tid & 31;
    const int i    = blockIdx.y;
    const int tile = blockIdx.x + tile_base;
    const int tile0 = tile * TILE_M;

    if (tid < NHID) { b0_s[tid] = b0[i * NHID + tid]; b1_s[tid] = b1[i * NHID + tid]; }
    if (tid < 128) W2_s[tid] = W2[i * 128 + tid];
    if (tid < 2)   b2_s[tid] = b2[i * 2 + tid];

    float d[8][4];
    #pragma unroll
    for (int q = 0; q < 8; ++q)
        #pragma unroll
        for (int c = 0; c < 4; ++c) d[q][c] = 0.f;

    // per-lane ldmatrix geometry
    const int rowA = (w << 4) + (lane & 15);
    const uint32_t aoff = (uint32_t)rowA * 128;
    const uint32_t axr  = (uint32_t)(rowA & 7) << 4;
    const int nB_ = lane & 15;
    const uint32_t bxr  = (uint32_t)(nB_ & 7) << 4;
    const uint32_t colsel = (uint32_t)(lane >> 4) << 4;

    auto prefetch = [&](int t) {
        const unsigned char* asrc = g_a + ((size_t)tile * 60 + i * 10 + t) * 32768;
        uint32_t adst = dynb + (uint32_t)(t & 1) * 32768;
        #pragma unroll
        for (int c = 0; c < 8; ++c)
            CP16(adst + tid * 16 + c * 4096, asrc + tid * 16 + c * 4096);
        const unsigned char* bsrc = g_w0bf + (size_t)(i * 10 + t) * 16384;
        uint32_t bdst = dynb + 65536 + (uint32_t)(t & 1) * 16384;
        #pragma unroll
        for (int c = 0; c < 4; ++c)
            CP16(bdst + tid * 16 + c * 4096, bsrc + tid * 16 + c * 4096);
        CP_COMMIT();
    };
    auto consume = [&](int s) {
        uint32_t Abase = dynb + (uint32_t)s * 32768;
        uint32_t Bbase = dynb + 65536 + (uint32_t)s * 16384;
        #pragma unroll
        for (int k = 0; k < 4; ++k) {
            uint32_t colb = (uint32_t)k * 32 + colsel;
            uint32_t aa = Abase + aoff + (colb ^ axr);
            uint32_t ah0, ah1, ah2, ah3, al0, al1, al2, al3;
            ldsm4(aa,         ah0, ah1, ah2, ah3);
            ldsm4(aa + 16384, al0, al1, al2, al3);
            #pragma unroll
            for (int g = 0; g < 4; ++g) {
                uint32_t ba = Bbase + ((uint32_t)g << 11) + (uint32_t)nB_ * 128 + (colb ^ bxr);
                uint32_t bh0, bh1, bh2, bh3, bl0, bl1, bl2, bl3;
                ldsm4(ba,        bh0, bh1, bh2, bh3);
                ldsm4(ba + 8192, bl0, bl1, bl2, bl3);
                mma_bf16(d[2 * g],     ah0, ah1, ah2, ah3, bh0, bh2);
                mma_bf16(d[2 * g],     al0, al1, al2, al3, bh0, bh2);
                mma_bf16(d[2 * g],     ah0, ah1, ah2, ah3, bl0, bl2);
                mma_bf16(d[2 * g + 1], ah0, ah1, ah2, ah3, bh1, bh3);
                mma_bf16(d[2 * g + 1], al0, al1, al2, al3, bh1, bh3);
                mma_bf16(d[2 * g + 1], ah0, ah1, ah2, ah3, bl1, bl3);
            }
        }
    };

    prefetch(0);
    prefetch(1);
    for (int t = 0; t < NTAU; ++t) {
        if (t < NTAU - 1) CP_WAIT1(); else CP_WAIT0();
        __syncthreads();
        consume(t & 1);
        __syncthreads();
        if (t < NTAU - 2) prefetch(t + 2);
    }

    // ---------- epilogue: bias+relu -> h_s (stride 68), stage W1 ----------
    {
        float* hs = (float*)dyn;
        int rb = (w << 4) + (lane >> 2);
        int cb = (lane & 3) * 2;
        #pragma unroll
        for (int nt = 0; nt < 8; ++nt) {
            int c = nt * 8 + cb;
            float ba = b0_s[c], bbv = b0_s[c + 1];
            *(float2*)&hs[rb * 68 + c]       = make_float2(fmaxf(d[nt][0] + ba, 0.f), fmaxf(d[nt][1] + bbv, 0.f));
            *(float2*)&hs[(rb + 8) * 68 + c] = make_float2(fmaxf(d[nt][2] + ba, 0.f), fmaxf(d[nt][3] + bbv, 0.f));
        }
        const unsigned char* w1src = (const unsigned char*)(W1 + (size_t)i * NHID * NHID);
        uint32_t w1dst = dynb + 65536;
        #pragma unroll
        for (int c = 0; c < 4; ++c)
            CP16(w1dst + tid * 16 + c * 4096, w1src + tid * 16 + c * 4096);
        CP_COMMIT();
        CP_WAIT0();
    }
    __syncthreads();

    // ---------- layers 1+2: 2 threads per token, split output-half ----------
    {
        const float* hs  = (const float*)dyn;
        const float* W1s = (const float*)(dyn + 65536);
        int r = tid >> 1, half = tid & 1;
        float h[NHID];
        {
            float4* hv = (float4*)h;
            const float4* src = (const float4*)(hs + r * 68);
            #pragma unroll
            for (int q = 0; q < 16; ++q) hv[q] = src[q];
        }
        ull acc2[16];
        #pragma unroll
        for (int p = 0; p < 16; ++p) acc2[p] = 0ULL;
        #pragma unroll 8
        for (int k = 0; k < NHID; ++k) {
            ull hdup = pack2(h[k]);
            const ulonglong2* wr = (const ulonglong2*)(W1s + k * NHID + half * 32);
            #pragma unroll
            for (int q = 0; q < 8; ++q) {
                ulonglong2 wv = wr[q];
                acc2[2 * q]     = ffma2(hdup, wv.x, acc2[2 * q]);
                acc2[2 * q + 1] = ffma2(hdup, wv.y, acc2[2 * q + 1]);
            }
        }
        float o0 = half ? 0.f : b2_s[0];
        float o1 = half ? 0.f : b2_s[1];
        #pragma unroll
        for (int p = 0; p < 16; ++p) {
            float2 v = unpack2(acc2[p]);
            int g0 = half * 32 + 2 * p;
            float v0 = fmaxf(v.x + b1_s[g0], 0.f);
            float v1 = fmaxf(v.y + b1_s[g0 + 1], 0.f);
            o0 = fmaf(v0, W2_s[g0 * 2],     o0);
            o1 = fmaf(v0, W2_s[g0 * 2 + 1], o1);
            o0 = fmaf(v1, W2_s[g0 * 2 + 2], o0);
            o1 = fmaf(v1, W2_s[g0 * 2 + 3], o1);
        }
        po_s[tid] = make_float2(o0, o1);
    }
    __syncthreads();
    if (tid < TILE_M) {
        float2 pa = po_s[2 * tid], pb = po_s[2 * tid + 1];
        int token = tile0 + tid;
        int bb = token & (NB - 1);
        int nn = token >> 4;
        ((float2*)out)[(size_t)(bb * ND + i) * NN + nn] = make_float2(pa.x + pb.x, pa.y + pb.y);
    }
}

extern "C" void kernel_launch(void* const* d_in, const int* in_sizes, int n_in,
                              void* d_out, int out_size)
{
    const float* x  = (const float*)d_in[0];
    const float* mp = (const float*)d_in[1];
    const float* u  = (const float*)d_in[2];
    const float* W0 = (const float*)d_in[3];
    const float* b0 = (const float*)d_in[4];
    const float* W1 = (const float*)d_in[5];
    const float* b1 = (const float*)d_in[6];
    const float* W2 = (const float*)d_in[7];
    const float* b2 = (const float*)d_in[8];
    float* out = (float*)d_out;

    static cudaStream_t s1;
    static cudaEvent_t evP[NCHUNK], evG;
    static int inited = 0;
    if (!inited) {
        cudaFuncSetAttribute(gemm_mlp, cudaFuncAttributeMaxDynamicSharedMemorySize, DYN_BYTES);
        cudaStreamCreateWithFlags(&s1, cudaStreamNonBlocking);
        for (int c = 0; c < NCHUNK; ++c)
            cudaEventCreateWithFlags(&evP[c], cudaEventDisableTiming);
        cudaEventCreateWithFlags(&evG, cudaEventDisableTiming);
        inited = 1;
    }

    // producer chain on the capture (default) stream; gemm chain on s1, each
    // gemm gated on its producer via event. Fork/join is graph-capturable.
    for (int c = 0; c < NCHUNK; ++c) {
        produce_a<<<dim3(CHUNK, 60), TPB, 0, 0>>>(x, mp, u, W0, c * CHUNK, c == 0);
        cudaEventRecord(evP[c], 0);
        cudaStreamWaitEvent(s1, evP[c], 0);
        gemm_mlp<<<dim3(CHUNK, ND), TPB, DYN_BYTES, s1>>>(b0, W1, b1, W2, b2, out, c * CHUNK);
    }
    cudaEventRecord(evG, s1);
    cudaStreamWaitEvent(0, evG, 0);   // join back into the captured stream
}